// round 16
// baseline (speedup 1.0000x reference)
#include <cuda_runtime.h>
#include <math.h>
#include <stdint.h>

#define S_LEN 2048
#define B_SZ  64
#define E_SZ  256
#define H_SZ  256
#define NWORK 48          // producer CTAs (64 + 48 = 112 SMs peak; DVFS probe)

// Scratch for x_proj: [S, B, H] fp32 = 134 MB
__device__ float g_xproj[(size_t)S_LEN * B_SZ * H_SZ];
// Per-step completion flags (zeroed each call)
__device__ int g_flag[S_LEN];

typedef unsigned long long ull;

// ---- packed f32x2 helpers ---------------------------------------------------
__device__ __forceinline__ ull fma2(ull a, ull b, ull c) {
    ull d;
    asm("fma.rn.f32x2 %0, %1, %2, %3;" : "=l"(d) : "l"(a), "l"(b), "l"(c));
    return d;
}
__device__ __forceinline__ ull add2(ull a, ull b) {
    ull d;
    asm("add.rn.f32x2 %0, %1, %2;" : "=l"(d) : "l"(a), "l"(b));
    return d;
}
__device__ __forceinline__ ull pack2(float lo, float hi) {
    ull d;
    asm("mov.b64 %0, {%1, %2};" : "=l"(d) : "f"(lo), "f"(hi));
    return d;
}
__device__ __forceinline__ void unpack2(ull v, float& lo, float& hi) {
    asm("mov.b64 {%0, %1}, %2;" : "=f"(lo), "=f"(hi) : "l"(v));
}

// fast tanh: tanh(x) = 1 - 2/(exp(2x)+1), via MUFU.EX2 + MUFU.RCP (~1e-6 err)
__device__ __forceinline__ float fast_tanh(float x) {
    float u, r;
    asm("ex2.approx.f32 %0, %1;" : "=f"(u) : "f"(x * 2.885390082f));
    asm("rcp.approx.f32 %0, %1;" : "=f"(r) : "f"(u + 1.0f));
    return fmaf(-2.0f, r, 1.0f);
}

// ---- release/acquire flag ops ----------------------------------------------
__device__ __forceinline__ int ld_acquire(const int* p) {
    int v;
    asm volatile("ld.acquire.gpu.global.b32 %0, [%1];" : "=r"(v) : "l"(p) : "memory");
    return v;
}
__device__ __forceinline__ void st_release(int* p, int v) {
    asm volatile("st.release.gpu.global.b32 [%0], %1;" :: "l"(p), "r"(v) : "memory");
}

__global__ void zero_flags() {
    const int i = blockIdx.x * blockDim.x + threadIdx.x;
    if (i < S_LEN) g_flag[i] = 0;
}

// ---------------------------------------------------------------------------
// Fused kernel, grid 112 x 512:
//   blockIdx <  64 : SCAN CTA (exact R13 structure — best measured)
//   blockIdx >= 64 : WORKER CTA (R12 v2: W_ih staged via SMEM, f32x2 FMAs),
//                    steps s = w, w+48, ... — stretched over the scan's
//                    shadow to cut peak co-resident power (DVFS probe).
// Sync: ONE ld.acquire per step by t0 (probe at top, confirm before BAR(A));
// reducers use plain LDG for x (hb chain: release -> acquire -> BAR).
// ---------------------------------------------------------------------------
#define K_REG  20
#define K_SMEM 12

__global__ __launch_bounds__(512, 1) void fused_kernel(
    const float* __restrict__ sent,   // [S*B, 256]
    const float* __restrict__ Wih,    // [256,256]
    const float* __restrict__ bias,   // [256]
    const float* __restrict__ Whh,    // [256,256]
    const float* __restrict__ h0,     // [64,256]
    float* __restrict__ out)          // [64,256]
{
    extern __shared__ ull smem[];
    const int t = threadIdx.x;

    if (blockIdx.x < B_SZ) {
        // =================== SCAN (exact R13) ==============================
        ulonglong2* sW   = (ulonglong2*)smem;
        ull*        part = (ull*)(smem + 8 * 12 * 64 * 2);
        ull*        hbuf = part + 8 * 128;

        const int b  = blockIdx.x;
        const int ks = t >> 6;
        const int jq = t & 63;
        const int kbase = ks * 32;

        ull wr[2 * K_REG];
        #pragma unroll
        for (int i = 0; i < K_REG; i++) {
            const int k = kbase + i;
            const ulonglong2 wv = *(const ulonglong2*)&Whh[(size_t)k * 256 + 4 * jq];
            wr[2 * i]     = wv.x;
            wr[2 * i + 1] = wv.y;
        }

        for (int idx = t; idx < 8 * K_SMEM * 64; idx += 512) {
            const int fjq = idx & 63;
            const int fm  = (idx >> 6) % K_SMEM;
            const int fks = idx / (K_SMEM * 64);
            const int k   = fks * 32 + K_REG + fm;
            sW[(fks * K_SMEM + fm) * 64 + fjq] =
                *(const ulonglong2*)&Whh[(size_t)k * 256 + 4 * fjq];
        }

        if (t < 256) {
            const float h = h0[(size_t)b * 256 + t];
            hbuf[t] = pack2(h, h);
        }

        // prologue: t0 waits for step 0's flag; BAR publishes ordering
        if (t == 0) {
            while (ld_acquire(&g_flag[0]) == 0) __nanosleep(64);
        }
        __syncthreads();

        ull xcur = 0;
        if (t < 128)
            xcur = *(const ull*)&g_xproj[((size_t)0 * B_SZ + b) * 256 + 2 * t];

        const ull* hb = hbuf + kbase;

        for (int s = 0; s < S_LEN; s++) {
            // t0: non-blocking probe of flag[s+1] (latency hidden by FMAs)
            int fv = 1;
            if (t == 0 && s + 1 < S_LEN) fv = ld_acquire(&g_flag[s + 1]);

            ull a01 = 0, a23 = 0;

            #pragma unroll
            for (int p = 0; p < K_REG / 2; p++) {
                const ulonglong2 hv = *(const ulonglong2*)(hb + 2 * p);
                a01 = fma2(wr[4 * p + 0], hv.x, a01);
                a23 = fma2(wr[4 * p + 1], hv.x, a23);
                a01 = fma2(wr[4 * p + 2], hv.y, a01);
                a23 = fma2(wr[4 * p + 3], hv.y, a23);
            }
            #pragma unroll
            for (int m = 0; m < K_SMEM; m += 2) {
                const ulonglong2 hv = *(const ulonglong2*)(hb + K_REG + m);
                const ulonglong2 w0 = sW[(ks * K_SMEM + m) * 64 + jq];
                const ulonglong2 w1 = sW[(ks * K_SMEM + m + 1) * 64 + jq];
                a01 = fma2(w0.x, hv.x, a01);
                a23 = fma2(w0.y, hv.x, a23);
                a01 = fma2(w1.x, hv.y, a01);
                a23 = fma2(w1.y, hv.y, a23);
            }

            part[ks * 128 + 2 * jq]     = a01;
            part[ks * 128 + 2 * jq + 1] = a23;

            // t0: confirm flag[s+1] before BAR(A) (poll only if behind)
            if (t == 0 && s + 1 < S_LEN) {
                while (fv == 0) {
                    __nanosleep(32);
                    fv = ld_acquire(&g_flag[s + 1]);
                }
            }
            __syncthreads();   // (A) partials visible; x[s+1] ordering done

            if (t < 128) {
                ull v = add2(add2(add2(part[0 * 128 + t], part[1 * 128 + t]),
                                  add2(part[2 * 128 + t], part[3 * 128 + t])),
                             add2(add2(part[4 * 128 + t], part[5 * 128 + t]),
                                  add2(part[6 * 128 + t], part[7 * 128 + t])));
                v = add2(v, xcur);
                float vx, vy;
                unpack2(v, vx, vy);
                const float tx = fast_tanh(vx);
                const float ty = fast_tanh(vy);
                hbuf[2 * t]     = pack2(tx, tx);
                hbuf[2 * t + 1] = pack2(ty, ty);

                // plain LDG prefetch of x[s+1]; consumed next step's reduce
                if (s + 1 < S_LEN)
                    xcur = *(const ull*)
                        &g_xproj[((size_t)(s + 1) * B_SZ + b) * 256 + 2 * t];
            }
            __syncthreads();   // (B) new h visible
        }

        if (t < 128) {
            float vx, vy, wx, wy;
            unpack2(hbuf[2 * t],     vx, vy);
            unpack2(hbuf[2 * t + 1], wx, wy);
            out[(size_t)b * 256 + 2 * t]     = vx;
            out[(size_t)b * 256 + 2 * t + 1] = wx;
        }
    } else {
        // =================== WORKER (R12 v2) ===============================
        float* xs = (float*)smem;
        ull*   Wc = (ull*)((char*)smem + 64 * 1024);

        const int w  = blockIdx.x - B_SZ;
        const int jq = t & 63;
        const int rg = t >> 6;

        const ull b01 = *(const ull*)&bias[4 * jq];
        const ull b23 = *(const ull*)&bias[4 * jq + 2];

        for (int s = w; s < S_LEN; s += NWORK) {
            {
                const float4* src = (const float4*)(sent + (size_t)s * 64 * 256);
                #pragma unroll
                for (int i = 0; i < 8; i++)
                    ((float4*)xs)[t + i * 512] = src[t + i * 512];
            }
            __syncthreads();

            ull acc0[8], acc1[8];
            #pragma unroll
            for (int r = 0; r < 8; r++) { acc0[r] = b01; acc1[r] = b23; }

            for (int c = 0; c < 8; c++) {
                if (c) __syncthreads();
                #pragma unroll
                for (int i = 0; i < 8; i++) {
                    const int idx = t + i * 512;
                    const int ik  = idx >> 7;
                    const int p   = idx & 127;
                    Wc[idx] = *(const ull*)&Wih[(size_t)(c * 32 + ik) * 256 + 2 * p];
                }
                __syncthreads();

                #pragma unroll
                for (int q = 0; q < 8; q++) {
                    float4 xv[8];
                    #pragma unroll
                    for (int r = 0; r < 8; r++)
                        xv[r] = *(const float4*)
                            &xs[(rg * 8 + r) * 256 + c * 32 + q * 4];
                    #pragma unroll
                    for (int e = 0; e < 4; e++) {
                        const ulonglong2 wv =
                            *(const ulonglong2*)&Wc[(q * 4 + e) * 128 + 2 * jq];
                        #pragma unroll
                        for (int r = 0; r < 8; r++) {
                            const float xe = (e == 0) ? xv[r].x :
                                             (e == 1) ? xv[r].y :
                                             (e == 2) ? xv[r].z : xv[r].w;
                            const ull xp = pack2(xe, xe);
                            acc0[r] = fma2(wv.x, xp, acc0[r]);
                            acc1[r] = fma2(wv.y, xp, acc1[r]);
                        }
                    }
                }
            }

            #pragma unroll
            for (int r = 0; r < 8; r++) {
                ull* dst = (ull*)&g_xproj[((size_t)s * 64 + rg * 8 + r) * 256 + 4 * jq];
                dst[0] = acc0[r];
                dst[1] = acc1[r];
            }
            __threadfence();
            __syncthreads();
            if (t == 0) st_release(&g_flag[s], 1);
        }
    }
}

// ---------------------------------------------------------------------------
extern "C" void kernel_launch(void* const* d_in, const int* in_sizes, int n_in,
                              void* d_out, int out_size)
{
    const float* sentence = (const float*)d_in[0];
    const float* h0       = (const float*)d_in[1];
    const float* W_ih     = (const float*)d_in[2];
    const float* W_hh     = (const float*)d_in[3];
    const float* bias     = (const float*)d_in[4];
    float* out = (float*)d_out;

    (void)in_sizes; (void)n_in; (void)out_size;

    zero_flags<<<(S_LEN + 511) / 512, 512>>>();

    // smem: scan sW 96KB + part 8KB + hbuf 2KB = 106 KB (worker: 96 KB)
    const int smem_bytes = (8 * K_SMEM * 64) * 16 + (8 * 128) * 8 + 256 * 8;
    cudaFuncSetAttribute(fused_kernel,
                         cudaFuncAttributeMaxDynamicSharedMemorySize,
                         smem_bytes);
    fused_kernel<<<B_SZ + NWORK, 512, smem_bytes>>>(
        sentence, W_ih, bias, W_hh, h0, out);
}

// round 17
// speedup vs baseline: 1.0590x; 1.0590x over previous
#include <cuda_runtime.h>
#include <math.h>
#include <stdint.h>

#define S_LEN 2048
#define B_SZ  64
#define E_SZ  256
#define H_SZ  256
#define NWORK 84          // producer CTAs (64 + 84 = 148 = full chip)

// Scratch for x_proj: [S, B, H] fp32 = 134 MB
__device__ float g_xproj[(size_t)S_LEN * B_SZ * H_SZ];
// Per-step completion flags + half-step counters (zeroed each call)
__device__ int g_flag[S_LEN];
__device__ int g_cnt[S_LEN];

typedef unsigned long long ull;

// ---- packed f32x2 helpers ---------------------------------------------------
__device__ __forceinline__ ull fma2(ull a, ull b, ull c) {
    ull d;
    asm("fma.rn.f32x2 %0, %1, %2, %3;" : "=l"(d) : "l"(a), "l"(b), "l"(c));
    return d;
}
__device__ __forceinline__ ull add2(ull a, ull b) {
    ull d;
    asm("add.rn.f32x2 %0, %1, %2;" : "=l"(d) : "l"(a), "l"(b));
    return d;
}
__device__ __forceinline__ ull pack2(float lo, float hi) {
    ull d;
    asm("mov.b64 %0, {%1, %2};" : "=l"(d) : "f"(lo), "f"(hi));
    return d;
}
__device__ __forceinline__ void unpack2(ull v, float& lo, float& hi) {
    asm("mov.b64 {%0, %1}, %2;" : "=f"(lo), "=f"(hi) : "l"(v));
}

// fast tanh: tanh(x) = 1 - 2/(exp(2x)+1), via MUFU.EX2 + MUFU.RCP (~1e-6 err)
__device__ __forceinline__ float fast_tanh(float x) {
    float u, r;
    asm("ex2.approx.f32 %0, %1;" : "=f"(u) : "f"(x * 2.885390082f));
    asm("rcp.approx.f32 %0, %1;" : "=f"(r) : "f"(u + 1.0f));
    return fmaf(-2.0f, r, 1.0f);
}

// ---- release/acquire sync ops ----------------------------------------------
__device__ __forceinline__ int ld_acquire(const int* p) {
    int v;
    asm volatile("ld.acquire.gpu.global.b32 %0, [%1];" : "=r"(v) : "l"(p) : "memory");
    return v;
}
__device__ __forceinline__ void st_release(int* p, int v) {
    asm volatile("st.release.gpu.global.b32 [%0], %1;" :: "l"(p), "r"(v) : "memory");
}
__device__ __forceinline__ int atom_add_release(int* p, int v) {
    int old;
    asm volatile("atom.add.release.gpu.global.s32 %0, [%1], %2;"
                 : "=r"(old) : "l"(p), "r"(v) : "memory");
    return old;
}

__global__ void zero_flags() {
    const int i = blockIdx.x * blockDim.x + threadIdx.x;
    if (i < S_LEN) { g_flag[i] = 0; g_cnt[i] = 0; }
}

// ---------------------------------------------------------------------------
// Fused kernel, grid 148 x 512 (one wave):
//   blockIdx <  64 : SCAN CTA — EXACT R13 structure (best measured).
//   blockIdx >= 64 : WORKER CTA — item = HALF-STEP (32 rows). 4096 items,
//     worker w takes items w, w+84, ... Per item: 32 sentence rows staged in
//     SMEM, W_ih staged per k-chunk (as R12), f32x2 FMAs. Step completion via
//     atom.add.release counter; 2nd finisher publishes g_flag[s] (release).
//     First flag ~9us (vs ~17 for whole-step items); 2x finer flag trickle.
// Scan sync: ONE ld.acquire per step by t0 (probe at top, confirm before
// BAR(A)); reducers use plain LDG for x (release -> acquire -> BAR chain).
// ---------------------------------------------------------------------------
#define K_REG  20
#define K_SMEM 12

__global__ __launch_bounds__(512, 1) void fused_kernel(
    const float* __restrict__ sent,   // [S*B, 256]
    const float* __restrict__ Wih,    // [256,256]
    const float* __restrict__ bias,   // [256]
    const float* __restrict__ Whh,    // [256,256]
    const float* __restrict__ h0,     // [64,256]
    float* __restrict__ out)          // [64,256]
{
    extern __shared__ ull smem[];
    const int t = threadIdx.x;

    if (blockIdx.x < B_SZ) {
        // =================== SCAN (exact R13) ==============================
        ulonglong2* sW   = (ulonglong2*)smem;
        ull*        part = (ull*)(smem + 8 * 12 * 64 * 2);
        ull*        hbuf = part + 8 * 128;

        const int b  = blockIdx.x;
        const int ks = t >> 6;
        const int jq = t & 63;
        const int kbase = ks * 32;

        ull wr[2 * K_REG];
        #pragma unroll
        for (int i = 0; i < K_REG; i++) {
            const int k = kbase + i;
            const ulonglong2 wv = *(const ulonglong2*)&Whh[(size_t)k * 256 + 4 * jq];
            wr[2 * i]     = wv.x;
            wr[2 * i + 1] = wv.y;
        }

        for (int idx = t; idx < 8 * K_SMEM * 64; idx += 512) {
            const int fjq = idx & 63;
            const int fm  = (idx >> 6) % K_SMEM;
            const int fks = idx / (K_SMEM * 64);
            const int k   = fks * 32 + K_REG + fm;
            sW[(fks * K_SMEM + fm) * 64 + fjq] =
                *(const ulonglong2*)&Whh[(size_t)k * 256 + 4 * fjq];
        }

        if (t < 256) {
            const float h = h0[(size_t)b * 256 + t];
            hbuf[t] = pack2(h, h);
        }

        // prologue: t0 waits for step 0's flag; BAR publishes ordering
        if (t == 0) {
            while (ld_acquire(&g_flag[0]) == 0) __nanosleep(64);
        }
        __syncthreads();

        ull xcur = 0;
        if (t < 128)
            xcur = *(const ull*)&g_xproj[((size_t)0 * B_SZ + b) * 256 + 2 * t];

        const ull* hb = hbuf + kbase;

        for (int s = 0; s < S_LEN; s++) {
            // t0: non-blocking probe of flag[s+1] (latency hidden by FMAs)
            int fv = 1;
            if (t == 0 && s + 1 < S_LEN) fv = ld_acquire(&g_flag[s + 1]);

            ull a01 = 0, a23 = 0;

            #pragma unroll
            for (int p = 0; p < K_REG / 2; p++) {
                const ulonglong2 hv = *(const ulonglong2*)(hb + 2 * p);
                a01 = fma2(wr[4 * p + 0], hv.x, a01);
                a23 = fma2(wr[4 * p + 1], hv.x, a23);
                a01 = fma2(wr[4 * p + 2], hv.y, a01);
                a23 = fma2(wr[4 * p + 3], hv.y, a23);
            }
            #pragma unroll
            for (int m = 0; m < K_SMEM; m += 2) {
                const ulonglong2 hv = *(const ulonglong2*)(hb + K_REG + m);
                const ulonglong2 w0 = sW[(ks * K_SMEM + m) * 64 + jq];
                const ulonglong2 w1 = sW[(ks * K_SMEM + m + 1) * 64 + jq];
                a01 = fma2(w0.x, hv.x, a01);
                a23 = fma2(w0.y, hv.x, a23);
                a01 = fma2(w1.x, hv.y, a01);
                a23 = fma2(w1.y, hv.y, a23);
            }

            part[ks * 128 + 2 * jq]     = a01;
            part[ks * 128 + 2 * jq + 1] = a23;

            // t0: confirm flag[s+1] before BAR(A) (poll only if behind)
            if (t == 0 && s + 1 < S_LEN) {
                while (fv == 0) {
                    __nanosleep(32);
                    fv = ld_acquire(&g_flag[s + 1]);
                }
            }
            __syncthreads();   // (A) partials visible; x[s+1] ordering done

            if (t < 128) {
                ull v = add2(add2(add2(part[0 * 128 + t], part[1 * 128 + t]),
                                  add2(part[2 * 128 + t], part[3 * 128 + t])),
                             add2(add2(part[4 * 128 + t], part[5 * 128 + t]),
                                  add2(part[6 * 128 + t], part[7 * 128 + t])));
                v = add2(v, xcur);
                float vx, vy;
                unpack2(v, vx, vy);
                const float tx = fast_tanh(vx);
                const float ty = fast_tanh(vy);
                hbuf[2 * t]     = pack2(tx, tx);
                hbuf[2 * t + 1] = pack2(ty, ty);

                // plain LDG prefetch of x[s+1]; consumed next step's reduce
                if (s + 1 < S_LEN)
                    xcur = *(const ull*)
                        &g_xproj[((size_t)(s + 1) * B_SZ + b) * 256 + 2 * t];
            }
            __syncthreads();   // (B) new h visible
        }

        if (t < 128) {
            float vx, vy, wx, wy;
            unpack2(hbuf[2 * t],     vx, vy);
            unpack2(hbuf[2 * t + 1], wx, wy);
            out[(size_t)b * 256 + 2 * t]     = vx;
            out[(size_t)b * 256 + 2 * t + 1] = wx;
        }
    } else {
        // =================== WORKER: half-step items =======================
        // smem: xs 32 rows x 256 f32 (32 KB) + Wc [32 k][128 col-pairs] ull
        // (32 KB). Thread t: jq = t&63 (cols 4jq..+3), rg = t>>6 (4 rows).
        float* xs = (float*)smem;
        ull*   Wc = (ull*)((char*)smem + 32 * 1024);

        const int w  = blockIdx.x - B_SZ;
        const int jq = t & 63;
        const int rg = t >> 6;

        const ull b01 = *(const ull*)&bias[4 * jq];
        const ull b23 = *(const ull*)&bias[4 * jq + 2];

        for (int i = w; i < 2 * S_LEN; i += NWORK) {
            const int s    = i >> 1;
            const int half = i & 1;
            const int row0 = half * 32;

            // load this item's 32 sentence rows (coalesced float4)
            {
                const float4* src = (const float4*)
                    (sent + ((size_t)s * 64 + row0) * 256);
                #pragma unroll
                for (int j = 0; j < 4; j++)
                    ((float4*)xs)[t + j * 512] = src[t + j * 512];
            }
            __syncthreads();   // xs ready (also: prev item's reads done)

            ull acc0[4], acc1[4];
            #pragma unroll
            for (int r = 0; r < 4; r++) { acc0[r] = b01; acc1[r] = b23; }

            for (int c = 0; c < 8; c++) {
                if (c) __syncthreads();          // prev chunk's Wc reads done
                #pragma unroll
                for (int j = 0; j < 8; j++) {
                    const int idx = t + j * 512;
                    const int ik  = idx >> 7;        // 0..31
                    const int p   = idx & 127;       // col-pair
                    Wc[idx] = *(const ull*)&Wih[(size_t)(c * 32 + ik) * 256 + 2 * p];
                }
                __syncthreads();                 // Wc ready

                #pragma unroll
                for (int q = 0; q < 8; q++) {
                    float4 xv[4];
                    #pragma unroll
                    for (int r = 0; r < 4; r++)
                        xv[r] = *(const float4*)
                            &xs[(rg * 4 + r) * 256 + c * 32 + q * 4];
                    #pragma unroll
                    for (int e = 0; e < 4; e++) {
                        const ulonglong2 wv =
                            *(const ulonglong2*)&Wc[(q * 4 + e) * 128 + 2 * jq];
                        #pragma unroll
                        for (int r = 0; r < 4; r++) {
                            const float xe = (e == 0) ? xv[r].x :
                                             (e == 1) ? xv[r].y :
                                             (e == 2) ? xv[r].z : xv[r].w;
                            const ull xp = pack2(xe, xe);
                            acc0[r] = fma2(wv.x, xp, acc0[r]);
                            acc1[r] = fma2(wv.y, xp, acc1[r]);
                        }
                    }
                }
            }

            // store 4 rows x 4 cols
            #pragma unroll
            for (int r = 0; r < 4; r++) {
                ull* dst = (ull*)&g_xproj[
                    ((size_t)s * 64 + row0 + rg * 4 + r) * 256 + 4 * jq];
                dst[0] = acc0[r];
                dst[1] = acc1[r];
            }
            __threadfence();   // this thread's stores visible gpu-wide
            __syncthreads();   // all threads of this item done
            if (t == 0) {
                // release-RMW on the step counter; 2nd finisher publishes the
                // flag (causality: both halves' fences precede their RMWs)
                const int old = atom_add_release(&g_cnt[s], 1);
                if (old == 1) st_release(&g_flag[s], 1);
            }
        }
    }
}

// ---------------------------------------------------------------------------
extern "C" void kernel_launch(void* const* d_in, const int* in_sizes, int n_in,
                              void* d_out, int out_size)
{
    const float* sentence = (const float*)d_in[0];
    const float* h0       = (const float*)d_in[1];
    const float* W_ih     = (const float*)d_in[2];
    const float* W_hh     = (const float*)d_in[3];
    const float* bias     = (const float*)d_in[4];
    float* out = (float*)d_out;

    (void)in_sizes; (void)n_in; (void)out_size;

    zero_flags<<<(S_LEN + 511) / 512, 512>>>();

    // smem: scan sW 96KB + part 8KB + hbuf 2KB = 106 KB (worker: 64 KB)
    const int smem_bytes = (8 * K_SMEM * 64) * 16 + (8 * 128) * 8 + 256 * 8;
    cudaFuncSetAttribute(fused_kernel,
                         cudaFuncAttributeMaxDynamicSharedMemorySize,
                         smem_bytes);
    fused_kernel<<<B_SZ + NWORK, 512, smem_bytes>>>(
        sentence, W_ih, bias, W_hh, h0, out);
}